// round 1
// baseline (speedup 1.0000x reference)
#include <cuda_runtime.h>
#include <math.h>

// Problem constants
#define BB   256
#define TT   512
#define IND  128
#define NI   149
#define NC   99
#define NM   8
#define CAT0 (IND + NI)   // 277
#define CAT1 (NI + NC)    // 248
#define CAT2 (NC + NM)    // 107
#define S0   160          // padded stride (128B aligned rows: 160*4 = 640 = 5*128)
#define S1   128          // 128*4 = 512 = 4*128
#define S2   8

// Precomputed fused/masked/transposed weights (device scratch; no allocs allowed)
__device__ float g_W0[3][CAT0 * S0];   // [mat][k*S0 + j], mat: 0=w1*m, 1=w2*m, 2=ts*wa+wb
__device__ float g_W1[3][CAT1 * S1];
__device__ float g_W2[3][CAT2 * S2];
__device__ float g_bc[NI + NC + NM];   // fused time bias ts*ba+bb per layer concat

// ---------------------------------------------------------------------------
// Precompute: mask w1/w2, fuse wa/wb with runtime scalar ts = dt[0], transpose.
// ---------------------------------------------------------------------------
__global__ void cfc_precompute_kernel(
    const float* __restrict__ w1_0, const float* __restrict__ w2_0,
    const float* __restrict__ wa_0, const float* __restrict__ wb_0,
    const float* __restrict__ ba_0, const float* __restrict__ bb_0,
    const int*   __restrict__ m0,
    const float* __restrict__ w1_1, const float* __restrict__ w2_1,
    const float* __restrict__ wa_1, const float* __restrict__ wb_1,
    const float* __restrict__ ba_1, const float* __restrict__ bb_1,
    const int*   __restrict__ m1,
    const float* __restrict__ w1_2, const float* __restrict__ w2_2,
    const float* __restrict__ wa_2, const float* __restrict__ wb_2,
    const float* __restrict__ ba_2, const float* __restrict__ bb_2,
    const int*   __restrict__ m2,
    const float* __restrict__ dt)
{
    const float ts = dt[0];
    const int idx    = blockIdx.x * blockDim.x + threadIdx.x;
    const int stride = gridDim.x * blockDim.x;

    for (int i = idx; i < CAT0 * NI; i += stride) {
        int k = i / NI, j = i - k * NI;
        int src = j * CAT0 + k;
        float mm = (float)m0[src];
        g_W0[0][k * S0 + j] = w1_0[src] * mm;
        g_W0[1][k * S0 + j] = w2_0[src] * mm;
        g_W0[2][k * S0 + j] = ts * wa_0[src] + wb_0[src];
    }
    for (int i = idx; i < CAT1 * NC; i += stride) {
        int k = i / NC, j = i - k * NC;
        int src = j * CAT1 + k;
        float mm = (float)m1[src];
        g_W1[0][k * S1 + j] = w1_1[src] * mm;
        g_W1[1][k * S1 + j] = w2_1[src] * mm;
        g_W1[2][k * S1 + j] = ts * wa_1[src] + wb_1[src];
    }
    for (int i = idx; i < CAT2 * NM; i += stride) {
        int k = i / NM, j = i - k * NM;
        int src = j * CAT2 + k;
        float mm = (float)m2[src];
        g_W2[0][k * S2 + j] = w1_2[src] * mm;
        g_W2[1][k * S2 + j] = w2_2[src] * mm;
        g_W2[2][k * S2 + j] = ts * wa_2[src] + wb_2[src];
    }
    for (int j = idx; j < NI; j += stride) g_bc[j]           = ts * ba_0[j] + bb_0[j];
    for (int j = idx; j < NC; j += stride) g_bc[NI + j]      = ts * ba_1[j] + bb_1[j];
    for (int j = idx; j < NM; j += stride) g_bc[NI + NC + j] = ts * ba_2[j] + bb_2[j];
}

// ---------------------------------------------------------------------------
// Main persistent kernel: 128 CTAs, each owns 2 batch rows for all 512 steps.
// Thread j computes output neuron j (all 3 fused matrices, both rows).
// ---------------------------------------------------------------------------
__device__ __forceinline__ float sigmoidf_(float z) {
    return 1.0f / (1.0f + expf(-z));
}

__global__ __launch_bounds__(160, 1) void cfc_main_kernel(
    const float* __restrict__ x,
    const float* __restrict__ b1_0, const float* __restrict__ b2_0,
    const float* __restrict__ b1_1, const float* __restrict__ b2_1,
    const float* __restrict__ b1_2, const float* __restrict__ b2_2,
    float* __restrict__ out, int write_h)
{
    __shared__ float sx[2][IND];
    __shared__ float sh0[2][NI];
    __shared__ float sh1[2][NC];
    __shared__ float sh2[2][NM];
    __shared__ float sw2[3 * CAT2 * S2];   // layer-2 weights cached (10.3 KB)

    const int tid = threadIdx.x;
    const int j = tid;
    const int b0 = blockIdx.x * 2;

    for (int i = tid; i < 3 * CAT2 * S2; i += blockDim.x)
        sw2[i] = ((const float*)g_W2)[i];
    for (int i = tid; i < 2 * NI; i += blockDim.x) ((float*)sh0)[i] = 0.0f;
    for (int i = tid; i < 2 * NC; i += blockDim.x) ((float*)sh1)[i] = 0.0f;
    for (int i = tid; i < 2 * NM; i += blockDim.x) ((float*)sh2)[i] = 0.0f;
    __syncthreads();

    for (int t = 0; t < TT; t++) {
        // stage x_t for both rows (coalesced)
        for (int i = tid; i < 2 * IND; i += blockDim.x) {
            int r = i >> 7, k = i & 127;
            sx[r][k] = x[((size_t)(b0 + r) * TT + t) * IND + k];
        }
        __syncthreads();

        // ---------------- layer 0: xh = [x_t | h0], hid = NI ----------------
        float n0a = 0.0f, n0b = 0.0f;
        if (j < NI) {
            float a1x = 0.f, a1y = 0.f, a2x = 0.f, a2y = 0.f, acx = 0.f, acy = 0.f;
            const float* W1 = g_W0[0] + j;
            const float* W2 = g_W0[1] + j;
            const float* W3 = g_W0[2] + j;
            #pragma unroll 8
            for (int k = 0; k < IND; k++) {
                float w1 = W1[k * S0], w2 = W2[k * S0], wc = W3[k * S0];
                float u = sx[0][k], v = sx[1][k];
                a1x = fmaf(w1, u, a1x); a1y = fmaf(w1, v, a1y);
                a2x = fmaf(w2, u, a2x); a2y = fmaf(w2, v, a2y);
                acx = fmaf(wc, u, acx); acy = fmaf(wc, v, acy);
            }
            #pragma unroll 4
            for (int k = 0; k < NI; k++) {
                float w1 = W1[(IND + k) * S0], w2 = W2[(IND + k) * S0], wc = W3[(IND + k) * S0];
                float u = sh0[0][k], v = sh0[1][k];
                a1x = fmaf(w1, u, a1x); a1y = fmaf(w1, v, a1y);
                a2x = fmaf(w2, u, a2x); a2y = fmaf(w2, v, a2y);
                acx = fmaf(wc, u, acx); acy = fmaf(wc, v, acy);
            }
            float bb1 = b1_0[j], bb2 = b2_0[j], bbc = g_bc[j];
            float t0 = sigmoidf_(acx + bbc);
            float t1 = sigmoidf_(acy + bbc);
            float f1a = tanhf(a1x + bb1), f1b = tanhf(a1y + bb1);
            float f2a = tanhf(a2x + bb2), f2b = tanhf(a2y + bb2);
            n0a = f1a * (1.0f - t0) + t0 * f2a;
            n0b = f1b * (1.0f - t1) + t1 * f2b;
        }
        __syncthreads();
        if (j < NI) { sh0[0][j] = n0a; sh0[1][j] = n0b; }
        __syncthreads();

        // ---------------- layer 1: xh = [nh0 | h1], hid = NC ----------------
        float n1a = 0.0f, n1b = 0.0f;
        if (j < NC) {
            float a1x = 0.f, a1y = 0.f, a2x = 0.f, a2y = 0.f, acx = 0.f, acy = 0.f;
            const float* W1 = g_W1[0] + j;
            const float* W2 = g_W1[1] + j;
            const float* W3 = g_W1[2] + j;
            #pragma unroll 4
            for (int k = 0; k < NI; k++) {
                float w1 = W1[k * S1], w2 = W2[k * S1], wc = W3[k * S1];
                float u = sh0[0][k], v = sh0[1][k];
                a1x = fmaf(w1, u, a1x); a1y = fmaf(w1, v, a1y);
                a2x = fmaf(w2, u, a2x); a2y = fmaf(w2, v, a2y);
                acx = fmaf(wc, u, acx); acy = fmaf(wc, v, acy);
            }
            #pragma unroll 4
            for (int k = 0; k < NC; k++) {
                float w1 = W1[(NI + k) * S1], w2 = W2[(NI + k) * S1], wc = W3[(NI + k) * S1];
                float u = sh1[0][k], v = sh1[1][k];
                a1x = fmaf(w1, u, a1x); a1y = fmaf(w1, v, a1y);
                a2x = fmaf(w2, u, a2x); a2y = fmaf(w2, v, a2y);
                acx = fmaf(wc, u, acx); acy = fmaf(wc, v, acy);
            }
            float bb1 = b1_1[j], bb2 = b2_1[j], bbc = g_bc[NI + j];
            float t0 = sigmoidf_(acx + bbc);
            float t1 = sigmoidf_(acy + bbc);
            float f1a = tanhf(a1x + bb1), f1b = tanhf(a1y + bb1);
            float f2a = tanhf(a2x + bb2), f2b = tanhf(a2y + bb2);
            n1a = f1a * (1.0f - t0) + t0 * f2a;
            n1b = f1b * (1.0f - t1) + t1 * f2b;
        }
        __syncthreads();
        if (j < NC) { sh1[0][j] = n1a; sh1[1][j] = n1b; }
        __syncthreads();

        // ---------------- layer 2: xh = [nh1 | h2], hid = NM ----------------
        float n2a = 0.0f, n2b = 0.0f;
        if (j < NM) {
            float a1x = 0.f, a1y = 0.f, a2x = 0.f, a2y = 0.f, acx = 0.f, acy = 0.f;
            const float* W1 = sw2 + 0 * CAT2 * S2 + j;
            const float* W2 = sw2 + 1 * CAT2 * S2 + j;
            const float* W3 = sw2 + 2 * CAT2 * S2 + j;
            #pragma unroll 4
            for (int k = 0; k < NC; k++) {
                float w1 = W1[k * S2], w2 = W2[k * S2], wc = W3[k * S2];
                float u = sh1[0][k], v = sh1[1][k];
                a1x = fmaf(w1, u, a1x); a1y = fmaf(w1, v, a1y);
                a2x = fmaf(w2, u, a2x); a2y = fmaf(w2, v, a2y);
                acx = fmaf(wc, u, acx); acy = fmaf(wc, v, acy);
            }
            #pragma unroll
            for (int k = 0; k < NM; k++) {
                float w1 = W1[(NC + k) * S2], w2 = W2[(NC + k) * S2], wc = W3[(NC + k) * S2];
                float u = sh2[0][k], v = sh2[1][k];
                a1x = fmaf(w1, u, a1x); a1y = fmaf(w1, v, a1y);
                a2x = fmaf(w2, u, a2x); a2y = fmaf(w2, v, a2y);
                acx = fmaf(wc, u, acx); acy = fmaf(wc, v, acy);
            }
            float bb1 = b1_2[j], bb2 = b2_2[j], bbc = g_bc[NI + NC + j];
            float t0 = sigmoidf_(acx + bbc);
            float t1 = sigmoidf_(acy + bbc);
            float f1a = tanhf(a1x + bb1), f1b = tanhf(a1y + bb1);
            float f2a = tanhf(a2x + bb2), f2b = tanhf(a2y + bb2);
            n2a = f1a * (1.0f - t0) + t0 * f2a;
            n2b = f1b * (1.0f - t1) + t1 * f2b;
            // y output: tanh saturation
            out[((size_t)(b0 + 0) * TT + t) * NM + j] = tanhf(n2a);
            out[((size_t)(b0 + 1) * TT + t) * NM + j] = tanhf(n2b);
        }
        __syncthreads();
        if (j < NM) { sh2[0][j] = n2a; sh2[1][j] = n2b; }
        __syncthreads();
    }

    // final hidden state: h_out[b] = [h0 | h1 | h2]  (256 units per row)
    if (write_h) {
        size_t base = (size_t)BB * TT * NM;
        size_t r0 = base + (size_t)(b0 + 0) * 256;
        size_t r1 = base + (size_t)(b0 + 1) * 256;
        if (j < NI) { out[r0 + j] = sh0[0][j];               out[r1 + j] = sh0[1][j]; }
        if (j < NC) { out[r0 + NI + j] = sh1[0][j];          out[r1 + NI + j] = sh1[1][j]; }
        if (j < NM) { out[r0 + NI + NC + j] = sh2[0][j];     out[r1 + NI + NC + j] = sh2[1][j]; }
    }
}

// ---------------------------------------------------------------------------
// Launch: detect input ordering (reference-signature order vs setup-dict order)
// ---------------------------------------------------------------------------
extern "C" void kernel_launch(void* const* d_in, const int* in_sizes, int n_in,
                              void* d_out, int out_size)
{
    const float *x, *dt;
    const float *w1[3], *b1[3], *w2[3], *b2[3], *wa[3], *ba[3], *wb[3], *bb[3];
    const int   *m[3];

    if (in_sizes[0] == BB * TT * IND) {
        // Order A: x, dt, then per layer (w1,b1,w2,b2,wa,ba,wb,bb,m)
        x  = (const float*)d_in[0];
        dt = (const float*)d_in[1];
        for (int l = 0; l < 3; l++) {
            int base = 2 + 9 * l;
            w1[l] = (const float*)d_in[base + 0];
            b1[l] = (const float*)d_in[base + 1];
            w2[l] = (const float*)d_in[base + 2];
            b2[l] = (const float*)d_in[base + 3];
            wa[l] = (const float*)d_in[base + 4];
            ba[l] = (const float*)d_in[base + 5];
            wb[l] = (const float*)d_in[base + 6];
            bb[l] = (const float*)d_in[base + 7];
            m[l]  = (const int*)  d_in[base + 8];
        }
    } else {
        // Order B (setup_inputs dict): per layer (w1,w2,wa,wb,b1,b2,ba,bb,m), then x, dt
        for (int l = 0; l < 3; l++) {
            int base = 9 * l;
            w1[l] = (const float*)d_in[base + 0];
            w2[l] = (const float*)d_in[base + 1];
            wa[l] = (const float*)d_in[base + 2];
            wb[l] = (const float*)d_in[base + 3];
            b1[l] = (const float*)d_in[base + 4];
            b2[l] = (const float*)d_in[base + 5];
            ba[l] = (const float*)d_in[base + 6];
            bb[l] = (const float*)d_in[base + 7];
            m[l]  = (const int*)  d_in[base + 8];
        }
        x  = (const float*)d_in[27];
        dt = (const float*)d_in[28];
    }

    cfc_precompute_kernel<<<148, 256>>>(
        w1[0], w2[0], wa[0], wb[0], ba[0], bb[0], m[0],
        w1[1], w2[1], wa[1], wb[1], ba[1], bb[1], m[1],
        w1[2], w2[2], wa[2], wb[2], ba[2], bb[2], m[2],
        dt);

    int write_h = (out_size >= BB * TT * NM + BB * 256) ? 1 : 0;
    cfc_main_kernel<<<BB / 2, 160>>>(
        x, b1[0], b2[0], b1[1], b2[1], b1[2], b2[2],
        (float*)d_out, write_h);
}

// round 2
// speedup vs baseline: 1.1391x; 1.1391x over previous
#include <cuda_runtime.h>
#include <math.h>

// Problem constants
#define BB   256
#define TT   512
#define IND  128
#define NI   149
#define NC   99
#define NM   8
#define CAT0 (IND + NI)   // 277
#define CAT1 (NI + NC)    // 248
#define CAT2 (NC + NM)    // 107
#define S0   160          // j-stride layer0 (640B rows)
#define S1   128          // j-stride layer1 (512B rows)
#define S2   8            // j-stride layer2
#define ROWS 4
#define NTH  480          // 3 mats x 160 j-slots, warp-aligned (5 warps per mat)

// Precomputed fused/masked/transposed weights
__device__ float g_W0[3][CAT0 * S0];
__device__ float g_W1[3][CAT1 * S1];
__device__ float g_W2[3][CAT2 * S2];
__device__ float g_bc[NI + NC + NM];   // ts*ba+bb fused bias

// ---------------------------------------------------------------------------
// Precompute: mask w1/w2, fuse wa/wb with ts = dt[0], transpose to [k][j].
// ---------------------------------------------------------------------------
__global__ void cfc_precompute_kernel(
    const float* __restrict__ w1_0, const float* __restrict__ w2_0,
    const float* __restrict__ wa_0, const float* __restrict__ wb_0,
    const float* __restrict__ ba_0, const float* __restrict__ bb_0,
    const int*   __restrict__ m0,
    const float* __restrict__ w1_1, const float* __restrict__ w2_1,
    const float* __restrict__ wa_1, const float* __restrict__ wb_1,
    const float* __restrict__ ba_1, const float* __restrict__ bb_1,
    const int*   __restrict__ m1,
    const float* __restrict__ w1_2, const float* __restrict__ w2_2,
    const float* __restrict__ wa_2, const float* __restrict__ wb_2,
    const float* __restrict__ ba_2, const float* __restrict__ bb_2,
    const int*   __restrict__ m2,
    const float* __restrict__ dt)
{
    const float ts = dt[0];
    const int idx    = blockIdx.x * blockDim.x + threadIdx.x;
    const int stride = gridDim.x * blockDim.x;

    for (int i = idx; i < CAT0 * NI; i += stride) {
        int k = i / NI, j = i - k * NI;
        int src = j * CAT0 + k;
        float mm = (float)m0[src];
        g_W0[0][k * S0 + j] = w1_0[src] * mm;
        g_W0[1][k * S0 + j] = w2_0[src] * mm;
        g_W0[2][k * S0 + j] = ts * wa_0[src] + wb_0[src];
    }
    for (int i = idx; i < CAT1 * NC; i += stride) {
        int k = i / NC, j = i - k * NC;
        int src = j * CAT1 + k;
        float mm = (float)m1[src];
        g_W1[0][k * S1 + j] = w1_1[src] * mm;
        g_W1[1][k * S1 + j] = w2_1[src] * mm;
        g_W1[2][k * S1 + j] = ts * wa_1[src] + wb_1[src];
    }
    for (int i = idx; i < CAT2 * NM; i += stride) {
        int k = i / NM, j = i - k * NM;
        int src = j * CAT2 + k;
        float mm = (float)m2[src];
        g_W2[0][k * S2 + j] = w1_2[src] * mm;
        g_W2[1][k * S2 + j] = w2_2[src] * mm;
        g_W2[2][k * S2 + j] = ts * wa_2[src] + wb_2[src];
    }
    for (int j = idx; j < NI; j += stride) g_bc[j]           = ts * ba_0[j] + bb_0[j];
    for (int j = idx; j < NC; j += stride) g_bc[NI + j]      = ts * ba_1[j] + bb_1[j];
    for (int j = idx; j < NM; j += stride) g_bc[NI + NC + j] = ts * ba_2[j] + bb_2[j];
}

// ---------------------------------------------------------------------------
// Packed fp32x2 helpers (Blackwell dual-fp32 path, PTX-only)
// ---------------------------------------------------------------------------
__device__ __forceinline__ unsigned long long pack2(float a, float b) {
    unsigned long long r;
    asm("mov.b64 %0, {%1, %2};" : "=l"(r) : "f"(a), "f"(b));
    return r;
}
__device__ __forceinline__ void unpack2(unsigned long long v, float& a, float& b) {
    asm("mov.b64 {%0, %1}, %2;" : "=f"(a), "=f"(b) : "l"(v));
}
__device__ __forceinline__ unsigned long long fma2(unsigned long long a,
                                                   unsigned long long b,
                                                   unsigned long long c) {
    unsigned long long d;
    asm("fma.rn.f32x2 %0, %1, %2, %3;" : "=l"(d) : "l"(a), "l"(b), "l"(c));
    return d;
}
__device__ __forceinline__ unsigned long long add2(unsigned long long a,
                                                   unsigned long long b) {
    unsigned long long d;
    asm("add.rn.f32x2 %0, %1, %2;" : "=l"(d) : "l"(a), "l"(b));
    return d;
}
__device__ __forceinline__ float sigmoidf_(float z) { return 1.0f / (1.0f + expf(-z)); }
__device__ __forceinline__ float cfc_mix(float a1, float a2, float ac,
                                         float b1, float b2, float bc) {
    float ff1 = tanhf(a1 + b1);
    float ff2 = tanhf(a2 + b2);
    float ti  = sigmoidf_(ac + bc);
    return ff1 + ti * (ff2 - ff1);
}

// ---------------------------------------------------------------------------
// Main persistent kernel: 64 CTAs x 480 threads; each CTA owns 4 batch rows
// for all 512 steps. Thread = (mat, j): one weight stream, 4 row-accumulators
// packed as 2x f32x2.
// ---------------------------------------------------------------------------
__global__ __launch_bounds__(NTH, 1) void cfc_main_kernel(
    const float* __restrict__ x,
    const float* __restrict__ b1_0, const float* __restrict__ b2_0,
    const float* __restrict__ b1_1, const float* __restrict__ b2_1,
    const float* __restrict__ b1_2, const float* __restrict__ b2_2,
    float* __restrict__ out, int write_h)
{
    // activations stored [k][row], 16B per k -> one LDS.128 feeds 4 rows
    __shared__ __align__(16) float xh0[CAT0 * 4];   // [x_t | h0]
    __shared__ __align__(16) float xh1[CAT1 * 4];   // [nh0 | h1]
    __shared__ __align__(16) float xh2[CAT2 * 4];   // [nh1 | h2]
    __shared__ __align__(16) float part [3][160 * 4];  // layer0/1 partials
    __shared__ __align__(16) float part2[3][160 * 4];  // layer2 partials
    __shared__ float sw2[3 * CAT2 * S2];               // layer2 weights (10.3KB)

    const int tid = threadIdx.x;
    const int mat = tid / 160;          // 0..2, warp-uniform
    const int jj  = tid - mat * 160;    // 0..159
    const int b0  = blockIdx.x * ROWS;

    // --- prologue: zero state, cache layer2 weights, preload biases -------
    for (int i = tid; i < CAT0 * 4; i += NTH) xh0[i] = 0.0f;
    for (int i = tid; i < CAT1 * 4; i += NTH) xh1[i] = 0.0f;
    for (int i = tid; i < CAT2 * 4; i += NTH) xh2[i] = 0.0f;
    for (int i = tid; i < 3 * CAT2 * S2; i += NTH) sw2[i] = ((const float*)g_W2)[i];

    float rb1_0 = 0.f, rb2_0 = 0.f, rbc_0 = 0.f;
    float rb1_1 = 0.f, rb2_1 = 0.f, rbc_1 = 0.f;
    float rb1_2 = 0.f, rb2_2 = 0.f, rbc_2 = 0.f;
    if (jj < NI) { rb1_0 = b1_0[jj]; rb2_0 = b2_0[jj]; rbc_0 = g_bc[jj]; }
    if (jj < NC) { rb1_1 = b1_1[jj]; rb2_1 = b2_1[jj]; rbc_1 = g_bc[NI + jj]; }
    if (jj < NM) { rb1_2 = b1_2[jj]; rb2_2 = b2_2[jj]; rbc_2 = g_bc[NI + NC + jj]; }

    // stage x_0, prefetch x_1 into registers
    const int i0 = tid, i1 = tid + NTH;           // i1 active only for tid<32
    for (int i = tid; i < ROWS * IND; i += NTH) {
        int r = i >> 7, k = i & 127;
        xh0[k * 4 + r] = x[((size_t)(b0 + r) * TT + 0) * IND + k];
    }
    float xr0 = x[((size_t)(b0 + (i0 >> 7)) * TT + 1) * IND + (i0 & 127)];
    float xr1 = 0.f;
    if (i1 < ROWS * IND)
        xr1 = x[((size_t)(b0 + (i1 >> 7)) * TT + 1) * IND + (i1 & 127)];
    __syncthreads();

    for (int t = 0; t < TT; ++t) {
        // ---------------- (a) layer 0 partials: k over CAT0 ----------------
        if (jj < NI) {
            const float* W = &g_W0[mat][jj];
            unsigned long long acc01 = 0ull, acc23 = 0ull;
            #pragma unroll 4
            for (int k = 0; k < CAT0; ++k) {
                float w = __ldg(W + k * S0);
                unsigned long long ww = pack2(w, w);
                ulonglong2 u = *(const ulonglong2*)&xh0[k * 4];
                acc01 = fma2(ww, u.x, acc01);
                acc23 = fma2(ww, u.y, acc23);
            }
            *(ulonglong2*)&part[mat][jj * 4] = make_ulonglong2(acc01, acc23);
        }
        __syncthreads();

        // ---------- (c) combine layer0 (row r=mat; mat0 also row3) + x restage
        if (jj < NI) {
            int r = (mat == 0) ? 0 : mat;
            float h = cfc_mix(part[0][jj * 4 + r], part[1][jj * 4 + r],
                              part[2][jj * 4 + r], rb1_0, rb2_0, rbc_0);
            xh0[(IND + jj) * 4 + r] = h;
            xh1[jj * 4 + r]         = h;
            if (mat == 0) {
                float h3 = cfc_mix(part[0][jj * 4 + 3], part[1][jj * 4 + 3],
                                   part[2][jj * 4 + 3], rb1_0, rb2_0, rbc_0);
                xh0[(IND + jj) * 4 + 3] = h3;
                xh1[jj * 4 + 3]         = h3;
            }
        }
        {   // store x_{t+1} from regs, prefetch x_{t+2}
            xh0[(i0 & 127) * 4 + (i0 >> 7)] = xr0;
            if (i1 < ROWS * IND) xh0[(i1 & 127) * 4 + (i1 >> 7)] = xr1;
            int tn = t + 2; if (tn > TT - 1) tn = TT - 1;
            xr0 = x[((size_t)(b0 + (i0 >> 7)) * TT + tn) * IND + (i0 & 127)];
            if (i1 < ROWS * IND)
                xr1 = x[((size_t)(b0 + (i1 >> 7)) * TT + tn) * IND + (i1 & 127)];
        }
        __syncthreads();

        // ---------------- (e) layer 1 partials: k over CAT1 ----------------
        if (jj < NC) {
            const float* W = &g_W1[mat][jj];
            unsigned long long acc01 = 0ull, acc23 = 0ull;
            #pragma unroll 4
            for (int k = 0; k < CAT1; ++k) {
                float w = __ldg(W + k * S1);
                unsigned long long ww = pack2(w, w);
                ulonglong2 u = *(const ulonglong2*)&xh1[k * 4];
                acc01 = fma2(ww, u.x, acc01);
                acc23 = fma2(ww, u.y, acc23);
            }
            *(ulonglong2*)&part[mat][jj * 4] = make_ulonglong2(acc01, acc23);
        }
        __syncthreads();

        // ---------- (g) combine layer1 ----------
        if (jj < NC) {
            int r = (mat == 0) ? 0 : mat;
            float h = cfc_mix(part[0][jj * 4 + r], part[1][jj * 4 + r],
                              part[2][jj * 4 + r], rb1_1, rb2_1, rbc_1);
            xh1[(NI + jj) * 4 + r] = h;
            xh2[jj * 4 + r]        = h;
            if (mat == 0) {
                float h3 = cfc_mix(part[0][jj * 4 + 3], part[1][jj * 4 + 3],
                                   part[2][jj * 4 + 3], rb1_1, rb2_1, rbc_1);
                xh1[(NI + jj) * 4 + 3] = h3;
                xh2[jj * 4 + 3]        = h3;
            }
        }
        __syncthreads();

        // ---------------- (i) layer 2 partials: k-split 20 chunks ----------
        {
            int j2 = jj & 7, kc = jj >> 3;       // 8 motors x 20 k-chunks
            int kb = kc * 6;
            int ke = kb + 6; if (ke > CAT2) ke = CAT2; if (kb > CAT2) kb = CAT2;
            unsigned long long acc01 = 0ull, acc23 = 0ull;
            const float* W = &sw2[mat * CAT2 * S2 + j2];
            for (int k = kb; k < ke; ++k) {
                float w = W[k * S2];
                unsigned long long ww = pack2(w, w);
                ulonglong2 u = *(const ulonglong2*)&xh2[k * 4];
                acc01 = fma2(ww, u.x, acc01);
                acc23 = fma2(ww, u.y, acc23);
            }
            *(ulonglong2*)&part2[mat][jj * 4] = make_ulonglong2(acc01, acc23);
        }
        __syncthreads();

        // ---------- (k) combine layer2: only 8 threads (mat0, jj<8) --------
        if (mat == 0 && jj < NM) {
            unsigned long long s0a = 0ull, s0b = 0ull;   // a1 rows 01 / 23
            unsigned long long s1a = 0ull, s1b = 0ull;   // a2
            unsigned long long s2a = 0ull, s2b = 0ull;   // ac
            #pragma unroll 4
            for (int kc = 0; kc < 20; ++kc) {
                int p = (kc * 8 + jj) * 4;
                ulonglong2 u0 = *(const ulonglong2*)&part2[0][p];
                ulonglong2 u1 = *(const ulonglong2*)&part2[1][p];
                ulonglong2 u2 = *(const ulonglong2*)&part2[2][p];
                s0a = add2(s0a, u0.x); s0b = add2(s0b, u0.y);
                s1a = add2(s1a, u1.x); s1b = add2(s1b, u1.y);
                s2a = add2(s2a, u2.x); s2b = add2(s2b, u2.y);
            }
            float a1[4], a2[4], ac[4];
            unpack2(s0a, a1[0], a1[1]); unpack2(s0b, a1[2], a1[3]);
            unpack2(s1a, a2[0], a2[1]); unpack2(s1b, a2[2], a2[3]);
            unpack2(s2a, ac[0], ac[1]); unpack2(s2b, ac[2], ac[3]);
            #pragma unroll
            for (int r = 0; r < 4; ++r) {
                float h = cfc_mix(a1[r], a2[r], ac[r], rb1_2, rb2_2, rbc_2);
                xh2[(NC + jj) * 4 + r] = h;
                out[((size_t)(b0 + r) * TT + t) * NM + jj] = tanhf(h);
            }
        }
        // no barrier needed here: next conflicting access (layer2 read of
        // xh2[NC+..] / write of part2) is behind two barriers; layer0 (a)
        // touches only xh0/part.
    }

    __syncthreads();
    if (write_h) {
        size_t base = (size_t)BB * TT * NM;
        int r = (mat == 0) ? 0 : mat;
        for (int pass = 0; pass < 2; ++pass) {
            int rr = (pass == 0) ? r : 3;
            if (pass == 1 && mat != 0) break;
            size_t ro = base + (size_t)(b0 + rr) * 256;
            if (jj < NI) out[ro + jj]           = xh0[(IND + jj) * 4 + rr];
            if (jj < NC) out[ro + NI + jj]      = xh1[(NI + jj) * 4 + rr];
            if (jj < NM) out[ro + NI + NC + jj] = xh2[(NC + jj) * 4 + rr];
        }
    }
}

// ---------------------------------------------------------------------------
// Launch: detect input ordering (reference-signature order vs setup-dict order)
// ---------------------------------------------------------------------------
extern "C" void kernel_launch(void* const* d_in, const int* in_sizes, int n_in,
                              void* d_out, int out_size)
{
    const float *x, *dt;
    const float *w1[3], *b1[3], *w2[3], *b2[3], *wa[3], *ba[3], *wb[3], *bb[3];
    const int   *m[3];

    if (in_sizes[0] == BB * TT * IND) {
        x  = (const float*)d_in[0];
        dt = (const float*)d_in[1];
        for (int l = 0; l < 3; l++) {
            int base = 2 + 9 * l;
            w1[l] = (const float*)d_in[base + 0];
            b1[l] = (const float*)d_in[base + 1];
            w2[l] = (const float*)d_in[base + 2];
            b2[l] = (const float*)d_in[base + 3];
            wa[l] = (const float*)d_in[base + 4];
            ba[l] = (const float*)d_in[base + 5];
            wb[l] = (const float*)d_in[base + 6];
            bb[l] = (const float*)d_in[base + 7];
            m[l]  = (const int*)  d_in[base + 8];
        }
    } else {
        for (int l = 0; l < 3; l++) {
            int base = 9 * l;
            w1[l] = (const float*)d_in[base + 0];
            w2[l] = (const float*)d_in[base + 1];
            wa[l] = (const float*)d_in[base + 2];
            wb[l] = (const float*)d_in[base + 3];
            b1[l] = (const float*)d_in[base + 4];
            b2[l] = (const float*)d_in[base + 5];
            ba[l] = (const float*)d_in[base + 6];
            bb[l] = (const float*)d_in[base + 7];
            m[l]  = (const int*)  d_in[base + 8];
        }
        x  = (const float*)d_in[27];
        dt = (const float*)d_in[28];
    }

    cfc_precompute_kernel<<<148, 256>>>(
        w1[0], w2[0], wa[0], wb[0], ba[0], bb[0], m[0],
        w1[1], w2[1], wa[1], wb[1], ba[1], bb[1], m[1],
        w1[2], w2[2], wa[2], wb[2], ba[2], bb[2], m[2],
        dt);

    int write_h = (out_size >= BB * TT * NM + BB * 256) ? 1 : 0;
    cfc_main_kernel<<<BB / ROWS, NTH>>>(
        x, b1[0], b2[0], b1[1], b2[1], b1[2], b2[2],
        (float*)d_out, write_h);
}

// round 3
// speedup vs baseline: 1.1425x; 1.0029x over previous
#include <cuda_runtime.h>
#include <math.h>

// Problem constants
#define BB   256
#define TT   512
#define IND  128
#define NI   149
#define NC   99
#define NM   8
#define CAT0 (IND + NI)   // 277
#define CAT1 (NI + NC)    // 248
#define CAT2 (NC + NM)    // 107
#define S0   160          // j-stride layer0 (640B rows)
#define S1   128          // j-stride layer1 (512B rows)
#define S2   8            // j-stride layer2
#define ROWS 4
#define NTH  480          // 3 mats x 160 j-slots, warp-aligned (5 warps per mat)

// Precomputed fused/masked/transposed weights
__device__ float g_W0[3][CAT0 * S0];
__device__ float g_W1[3][CAT1 * S1];
__device__ float g_W2[3][CAT2 * S2];
__device__ float g_bc[NI + NC + NM];   // ts*ba+bb fused bias

// ---------------------------------------------------------------------------
// Precompute: mask w1/w2, fuse wa/wb with ts = dt[0], transpose to [k][j].
// ---------------------------------------------------------------------------
__global__ void cfc_precompute_kernel(
    const float* __restrict__ w1_0, const float* __restrict__ w2_0,
    const float* __restrict__ wa_0, const float* __restrict__ wb_0,
    const float* __restrict__ ba_0, const float* __restrict__ bb_0,
    const int*   __restrict__ m0,
    const float* __restrict__ w1_1, const float* __restrict__ w2_1,
    const float* __restrict__ wa_1, const float* __restrict__ wb_1,
    const float* __restrict__ ba_1, const float* __restrict__ bb_1,
    const int*   __restrict__ m1,
    const float* __restrict__ w1_2, const float* __restrict__ w2_2,
    const float* __restrict__ wa_2, const float* __restrict__ wb_2,
    const float* __restrict__ ba_2, const float* __restrict__ bb_2,
    const int*   __restrict__ m2,
    const float* __restrict__ dt)
{
    const float ts = dt[0];
    const int idx    = blockIdx.x * blockDim.x + threadIdx.x;
    const int stride = gridDim.x * blockDim.x;

    for (int i = idx; i < CAT0 * NI; i += stride) {
        int k = i / NI, j = i - k * NI;
        int src = j * CAT0 + k;
        float mm = (float)m0[src];
        g_W0[0][k * S0 + j] = w1_0[src] * mm;
        g_W0[1][k * S0 + j] = w2_0[src] * mm;
        g_W0[2][k * S0 + j] = ts * wa_0[src] + wb_0[src];
    }
    for (int i = idx; i < CAT1 * NC; i += stride) {
        int k = i / NC, j = i - k * NC;
        int src = j * CAT1 + k;
        float mm = (float)m1[src];
        g_W1[0][k * S1 + j] = w1_1[src] * mm;
        g_W1[1][k * S1 + j] = w2_1[src] * mm;
        g_W1[2][k * S1 + j] = ts * wa_1[src] + wb_1[src];
    }
    for (int i = idx; i < CAT2 * NM; i += stride) {
        int k = i / NM, j = i - k * NM;
        int src = j * CAT2 + k;
        float mm = (float)m2[src];
        g_W2[0][k * S2 + j] = w1_2[src] * mm;
        g_W2[1][k * S2 + j] = w2_2[src] * mm;
        g_W2[2][k * S2 + j] = ts * wa_2[src] + wb_2[src];
    }
    for (int j = idx; j < NI; j += stride) g_bc[j]           = ts * ba_0[j] + bb_0[j];
    for (int j = idx; j < NC; j += stride) g_bc[NI + j]      = ts * ba_1[j] + bb_1[j];
    for (int j = idx; j < NM; j += stride) g_bc[NI + NC + j] = ts * ba_2[j] + bb_2[j];
}

// ---------------------------------------------------------------------------
// Packed fp32x2 helpers (Blackwell dual-fp32 path, PTX-only)
// ---------------------------------------------------------------------------
__device__ __forceinline__ unsigned long long pack2(float a, float b) {
    unsigned long long r;
    asm("mov.b64 %0, {%1, %2};" : "=l"(r) : "f"(a), "f"(b));
    return r;
}
__device__ __forceinline__ void unpack2(unsigned long long v, float& a, float& b) {
    asm("mov.b64 {%0, %1}, %2;" : "=f"(a), "=f"(b) : "l"(v));
}
__device__ __forceinline__ unsigned long long fma2(unsigned long long a,
                                                   unsigned long long b,
                                                   unsigned long long c) {
    unsigned long long d;
    asm("fma.rn.f32x2 %0, %1, %2, %3;" : "=l"(d) : "l"(a), "l"(b), "l"(c));
    return d;
}
__device__ __forceinline__ unsigned long long add2(unsigned long long a,
                                                   unsigned long long b) {
    unsigned long long d;
    asm("add.rn.f32x2 %0, %1, %2;" : "=l"(d) : "l"(a), "l"(b));
    return d;
}
__device__ __forceinline__ float sigmoidf_(float z) { return 1.0f / (1.0f + expf(-z)); }
__device__ __forceinline__ float cfc_mix(float a1, float a2, float ac,
                                         float b1, float b2, float bc) {
    float ff1 = tanhf(a1 + b1);
    float ff2 = tanhf(a2 + b2);
    float ti  = sigmoidf_(ac + bc);
    return ff1 + ti * (ff2 - ff1);
}

// ---------------------------------------------------------------------------
// Main persistent kernel: 64 CTAs x 480 threads; each CTA owns 4 batch rows
// for all 512 steps. Thread = (mat, j): one weight stream, 4 row-accumulators
// packed as 2x f32x2.
// ---------------------------------------------------------------------------
__global__ __launch_bounds__(NTH, 1) void cfc_main_kernel(
    const float* __restrict__ x,
    const float* __restrict__ b1_0, const float* __restrict__ b2_0,
    const float* __restrict__ b1_1, const float* __restrict__ b2_1,
    const float* __restrict__ b1_2, const float* __restrict__ b2_2,
    float* __restrict__ out, int write_h)
{
    // activations stored [k][row], 16B per k -> one LDS.128 feeds 4 rows
    __shared__ __align__(16) float xh0[CAT0 * 4];   // [x_t | h0]
    __shared__ __align__(16) float xh1[CAT1 * 4];   // [nh0 | h1]
    __shared__ __align__(16) float xh2[CAT2 * 4];   // [nh1 | h2]
    __shared__ __align__(16) float part [3][160 * 4];  // layer0/1 partials
    __shared__ __align__(16) float part2[3][160 * 4];  // layer2 partials
    __shared__ float sw2[3 * CAT2 * S2];               // layer2 weights (10.3KB)

    const int tid = threadIdx.x;
    const int mat = tid / 160;          // 0..2, warp-uniform
    const int jj  = tid - mat * 160;    // 0..159
    const int b0  = blockIdx.x * ROWS;

    // --- prologue: zero state, cache layer2 weights, preload biases -------
    for (int i = tid; i < CAT0 * 4; i += NTH) xh0[i] = 0.0f;
    for (int i = tid; i < CAT1 * 4; i += NTH) xh1[i] = 0.0f;
    for (int i = tid; i < CAT2 * 4; i += NTH) xh2[i] = 0.0f;
    for (int i = tid; i < 3 * CAT2 * S2; i += NTH) sw2[i] = ((const float*)g_W2)[i];

    float rb1_0 = 0.f, rb2_0 = 0.f, rbc_0 = 0.f;
    float rb1_1 = 0.f, rb2_1 = 0.f, rbc_1 = 0.f;
    float rb1_2 = 0.f, rb2_2 = 0.f, rbc_2 = 0.f;
    if (jj < NI) { rb1_0 = b1_0[jj]; rb2_0 = b2_0[jj]; rbc_0 = g_bc[jj]; }
    if (jj < NC) { rb1_1 = b1_1[jj]; rb2_1 = b2_1[jj]; rbc_1 = g_bc[NI + jj]; }
    if (jj < NM) { rb1_2 = b1_2[jj]; rb2_2 = b2_2[jj]; rbc_2 = g_bc[NI + NC + jj]; }

    // stage x_0, prefetch x_1 into registers
    const int i0 = tid, i1 = tid + NTH;           // i1 active only for tid<32
    for (int i = tid; i < ROWS * IND; i += NTH) {
        int r = i >> 7, k = i & 127;
        xh0[k * 4 + r] = x[((size_t)(b0 + r) * TT + 0) * IND + k];
    }
    float xr0 = x[((size_t)(b0 + (i0 >> 7)) * TT + 1) * IND + (i0 & 127)];
    float xr1 = 0.f;
    if (i1 < ROWS * IND)
        xr1 = x[((size_t)(b0 + (i1 >> 7)) * TT + 1) * IND + (i1 & 127)];
    __syncthreads();

    for (int t = 0; t < TT; ++t) {
        // ---------------- (a) layer 0 partials: k over CAT0 ----------------
        if (jj < NI) {
            const float* W = &g_W0[mat][jj];
            unsigned long long acc01 = 0ull, acc23 = 0ull;
            #pragma unroll 4
            for (int k = 0; k < CAT0; ++k) {
                float w = __ldg(W + k * S0);
                unsigned long long ww = pack2(w, w);
                ulonglong2 u = *(const ulonglong2*)&xh0[k * 4];
                acc01 = fma2(ww, u.x, acc01);
                acc23 = fma2(ww, u.y, acc23);
            }
            *(ulonglong2*)&part[mat][jj * 4] = make_ulonglong2(acc01, acc23);
        }
        __syncthreads();

        // ---------- (c) combine layer0 (row r=mat; mat0 also row3) + x restage
        if (jj < NI) {
            int r = (mat == 0) ? 0 : mat;
            float h = cfc_mix(part[0][jj * 4 + r], part[1][jj * 4 + r],
                              part[2][jj * 4 + r], rb1_0, rb2_0, rbc_0);
            xh0[(IND + jj) * 4 + r] = h;
            xh1[jj * 4 + r]         = h;
            if (mat == 0) {
                float h3 = cfc_mix(part[0][jj * 4 + 3], part[1][jj * 4 + 3],
                                   part[2][jj * 4 + 3], rb1_0, rb2_0, rbc_0);
                xh0[(IND + jj) * 4 + 3] = h3;
                xh1[jj * 4 + 3]         = h3;
            }
        }
        {   // store x_{t+1} from regs, prefetch x_{t+2}
            xh0[(i0 & 127) * 4 + (i0 >> 7)] = xr0;
            if (i1 < ROWS * IND) xh0[(i1 & 127) * 4 + (i1 >> 7)] = xr1;
            int tn = t + 2; if (tn > TT - 1) tn = TT - 1;
            xr0 = x[((size_t)(b0 + (i0 >> 7)) * TT + tn) * IND + (i0 & 127)];
            if (i1 < ROWS * IND)
                xr1 = x[((size_t)(b0 + (i1 >> 7)) * TT + tn) * IND + (i1 & 127)];
        }
        __syncthreads();

        // ---------------- (e) layer 1 partials: k over CAT1 ----------------
        if (jj < NC) {
            const float* W = &g_W1[mat][jj];
            unsigned long long acc01 = 0ull, acc23 = 0ull;
            #pragma unroll 4
            for (int k = 0; k < CAT1; ++k) {
                float w = __ldg(W + k * S1);
                unsigned long long ww = pack2(w, w);
                ulonglong2 u = *(const ulonglong2*)&xh1[k * 4];
                acc01 = fma2(ww, u.x, acc01);
                acc23 = fma2(ww, u.y, acc23);
            }
            *(ulonglong2*)&part[mat][jj * 4] = make_ulonglong2(acc01, acc23);
        }
        __syncthreads();

        // ---------- (g) combine layer1 ----------
        if (jj < NC) {
            int r = (mat == 0) ? 0 : mat;
            float h = cfc_mix(part[0][jj * 4 + r], part[1][jj * 4 + r],
                              part[2][jj * 4 + r], rb1_1, rb2_1, rbc_1);
            xh1[(NI + jj) * 4 + r] = h;
            xh2[jj * 4 + r]        = h;
            if (mat == 0) {
                float h3 = cfc_mix(part[0][jj * 4 + 3], part[1][jj * 4 + 3],
                                   part[2][jj * 4 + 3], rb1_1, rb2_1, rbc_1);
                xh1[(NI + jj) * 4 + 3] = h3;
                xh2[jj * 4 + 3]        = h3;
            }
        }
        __syncthreads();

        // ---------------- (i) layer 2 partials: k-split 20 chunks ----------
        {
            int j2 = jj & 7, kc = jj >> 3;       // 8 motors x 20 k-chunks
            int kb = kc * 6;
            int ke = kb + 6; if (ke > CAT2) ke = CAT2; if (kb > CAT2) kb = CAT2;
            unsigned long long acc01 = 0ull, acc23 = 0ull;
            const float* W = &sw2[mat * CAT2 * S2 + j2];
            for (int k = kb; k < ke; ++k) {
                float w = W[k * S2];
                unsigned long long ww = pack2(w, w);
                ulonglong2 u = *(const ulonglong2*)&xh2[k * 4];
                acc01 = fma2(ww, u.x, acc01);
                acc23 = fma2(ww, u.y, acc23);
            }
            *(ulonglong2*)&part2[mat][jj * 4] = make_ulonglong2(acc01, acc23);
        }
        __syncthreads();

        // ---------- (k) combine layer2: only 8 threads (mat0, jj<8) --------
        if (mat == 0 && jj < NM) {
            unsigned long long s0a = 0ull, s0b = 0ull;   // a1 rows 01 / 23
            unsigned long long s1a = 0ull, s1b = 0ull;   // a2
            unsigned long long s2a = 0ull, s2b = 0ull;   // ac
            #pragma unroll 4
            for (int kc = 0; kc < 20; ++kc) {
                int p = (kc * 8 + jj) * 4;
                ulonglong2 u0 = *(const ulonglong2*)&part2[0][p];
                ulonglong2 u1 = *(const ulonglong2*)&part2[1][p];
                ulonglong2 u2 = *(const ulonglong2*)&part2[2][p];
                s0a = add2(s0a, u0.x); s0b = add2(s0b, u0.y);
                s1a = add2(s1a, u1.x); s1b = add2(s1b, u1.y);
                s2a = add2(s2a, u2.x); s2b = add2(s2b, u2.y);
            }
            float a1[4], a2[4], ac[4];
            unpack2(s0a, a1[0], a1[1]); unpack2(s0b, a1[2], a1[3]);
            unpack2(s1a, a2[0], a2[1]); unpack2(s1b, a2[2], a2[3]);
            unpack2(s2a, ac[0], ac[1]); unpack2(s2b, ac[2], ac[3]);
            #pragma unroll
            for (int r = 0; r < 4; ++r) {
                float h = cfc_mix(a1[r], a2[r], ac[r], rb1_2, rb2_2, rbc_2);
                xh2[(NC + jj) * 4 + r] = h;
                out[((size_t)(b0 + r) * TT + t) * NM + jj] = tanhf(h);
            }
        }
        // no barrier needed here: next conflicting access (layer2 read of
        // xh2[NC+..] / write of part2) is behind two barriers; layer0 (a)
        // touches only xh0/part.
    }

    __syncthreads();
    if (write_h) {
        size_t base = (size_t)BB * TT * NM;
        int r = (mat == 0) ? 0 : mat;
        for (int pass = 0; pass < 2; ++pass) {
            int rr = (pass == 0) ? r : 3;
            if (pass == 1 && mat != 0) break;
            size_t ro = base + (size_t)(b0 + rr) * 256;
            if (jj < NI) out[ro + jj]           = xh0[(IND + jj) * 4 + rr];
            if (jj < NC) out[ro + NI + jj]      = xh1[(NI + jj) * 4 + rr];
            if (jj < NM) out[ro + NI + NC + jj] = xh2[(NC + jj) * 4 + rr];
        }
    }
}

// ---------------------------------------------------------------------------
// Launch: detect input ordering (reference-signature order vs setup-dict order)
// ---------------------------------------------------------------------------
extern "C" void kernel_launch(void* const* d_in, const int* in_sizes, int n_in,
                              void* d_out, int out_size)
{
    const float *x, *dt;
    const float *w1[3], *b1[3], *w2[3], *b2[3], *wa[3], *ba[3], *wb[3], *bb[3];
    const int   *m[3];

    if (in_sizes[0] == BB * TT * IND) {
        x  = (const float*)d_in[0];
        dt = (const float*)d_in[1];
        for (int l = 0; l < 3; l++) {
            int base = 2 + 9 * l;
            w1[l] = (const float*)d_in[base + 0];
            b1[l] = (const float*)d_in[base + 1];
            w2[l] = (const float*)d_in[base + 2];
            b2[l] = (const float*)d_in[base + 3];
            wa[l] = (const float*)d_in[base + 4];
            ba[l] = (const float*)d_in[base + 5];
            wb[l] = (const float*)d_in[base + 6];
            bb[l] = (const float*)d_in[base + 7];
            m[l]  = (const int*)  d_in[base + 8];
        }
    } else {
        for (int l = 0; l < 3; l++) {
            int base = 9 * l;
            w1[l] = (const float*)d_in[base + 0];
            w2[l] = (const float*)d_in[base + 1];
            wa[l] = (const float*)d_in[base + 2];
            wb[l] = (const float*)d_in[base + 3];
            b1[l] = (const float*)d_in[base + 4];
            b2[l] = (const float*)d_in[base + 5];
            ba[l] = (const float*)d_in[base + 6];
            bb[l] = (const float*)d_in[base + 7];
            m[l]  = (const int*)  d_in[base + 8];
        }
        x  = (const float*)d_in[27];
        dt = (const float*)d_in[28];
    }

    cfc_precompute_kernel<<<148, 256>>>(
        w1[0], w2[0], wa[0], wb[0], ba[0], bb[0], m[0],
        w1[1], w2[1], wa[1], wb[1], ba[1], bb[1], m[1],
        w1[2], w2[2], wa[2], wb[2], ba[2], bb[2], m[2],
        dt);

    int write_h = (out_size >= BB * TT * NM + BB * 256) ? 1 : 0;
    cfc_main_kernel<<<BB / ROWS, NTH>>>(
        x, b1[0], b2[0], b1[1], b2[1], b1[2], b2[2],
        (float*)d_out, write_h);
}

// round 4
// speedup vs baseline: 2.5759x; 2.2547x over previous
#include <cuda_runtime.h>
#include <math.h>

// Problem constants
#define BB   256
#define TT   512
#define IND  128
#define NI   149
#define NC   99
#define NM   8
#define CAT0 (IND + NI)   // 277
#define CAT1 (NI + NC)    // 248
#define CAT2 (NC + NM)    // 107
#define S0   160          // padded j-stride layer0
#define S1   128          // padded j-stride layer1
#define S2   8            // j-stride layer2
#define ROWS 4
#define NTH  480

// SMEM layout (floats)
#define OFF_XH0   0                 // 277*8 = 2216 (dup: a0,a0,a1,a1,a2,a2,a3,a3)
#define OFF_XH1   2216              // 248*8 = 1984
#define OFF_XH2   4200              // 110*4 = 440  (plain [k][4rows])
#define OFF_PART  4640              // 9216
#define OFF_PART2 13856             // 3*160*4 = 1920
#define OFF_SW2   15776             // 3*107*8 = 2568
#define SMEM_FLOATS 18344
#define SMEM_BYTES  (SMEM_FLOATS * 4)

// Precomputed fused/masked/transposed weights (padded j zeroed)
__device__ float g_W0[3][CAT0 * S0];
__device__ float g_W1[3][CAT1 * S1];
__device__ float g_W2[3][CAT2 * S2];
__device__ float g_bc[NI + NC + NM];

// ---------------------------------------------------------------------------
__global__ void cfc_precompute_kernel(
    const float* __restrict__ w1_0, const float* __restrict__ w2_0,
    const float* __restrict__ wa_0, const float* __restrict__ wb_0,
    const float* __restrict__ ba_0, const float* __restrict__ bb_0,
    const int*   __restrict__ m0,
    const float* __restrict__ w1_1, const float* __restrict__ w2_1,
    const float* __restrict__ wa_1, const float* __restrict__ wb_1,
    const float* __restrict__ ba_1, const float* __restrict__ bb_1,
    const int*   __restrict__ m1,
    const float* __restrict__ w1_2, const float* __restrict__ w2_2,
    const float* __restrict__ wa_2, const float* __restrict__ wb_2,
    const float* __restrict__ ba_2, const float* __restrict__ bb_2,
    const int*   __restrict__ m2,
    const float* __restrict__ dt)
{
    const float ts = dt[0];
    const int idx    = blockIdx.x * blockDim.x + threadIdx.x;
    const int stride = gridDim.x * blockDim.x;

    for (int i = idx; i < CAT0 * S0; i += stride) {
        int k = i / S0, j = i - k * S0;
        float v1 = 0.f, v2 = 0.f, vc = 0.f;
        if (j < NI) {
            int src = j * CAT0 + k;
            float mm = (float)m0[src];
            v1 = w1_0[src] * mm;
            v2 = w2_0[src] * mm;
            vc = ts * wa_0[src] + wb_0[src];
        }
        g_W0[0][i] = v1; g_W0[1][i] = v2; g_W0[2][i] = vc;
    }
    for (int i = idx; i < CAT1 * S1; i += stride) {
        int k = i / S1, j = i - k * S1;
        float v1 = 0.f, v2 = 0.f, vc = 0.f;
        if (j < NC) {
            int src = j * CAT1 + k;
            float mm = (float)m1[src];
            v1 = w1_1[src] * mm;
            v2 = w2_1[src] * mm;
            vc = ts * wa_1[src] + wb_1[src];
        }
        g_W1[0][i] = v1; g_W1[1][i] = v2; g_W1[2][i] = vc;
    }
    for (int i = idx; i < CAT2 * S2; i += stride) {
        int k = i / S2, j = i - k * S2;
        int src = j * CAT2 + k;
        float mm = (float)m2[src];
        g_W2[0][i] = w1_2[src] * mm;
        g_W2[1][i] = w2_2[src] * mm;
        g_W2[2][i] = ts * wa_2[src] + wb_2[src];
    }
    for (int j = idx; j < NI; j += stride) g_bc[j]           = ts * ba_0[j] + bb_0[j];
    for (int j = idx; j < NC; j += stride) g_bc[NI + j]      = ts * ba_1[j] + bb_1[j];
    for (int j = idx; j < NM; j += stride) g_bc[NI + NC + j] = ts * ba_2[j] + bb_2[j];
}

// ---------------------------------------------------------------------------
// Packed fp32x2 helpers
// ---------------------------------------------------------------------------
__device__ __forceinline__ unsigned long long pack2(float a, float b) {
    unsigned long long r;
    asm("mov.b64 %0, {%1, %2};" : "=l"(r) : "f"(a), "f"(b));
    return r;
}
__device__ __forceinline__ void unpack2(unsigned long long v, float& a, float& b) {
    asm("mov.b64 {%0, %1}, %2;" : "=f"(a), "=f"(b) : "l"(v));
}
__device__ __forceinline__ unsigned long long fma2(unsigned long long a,
                                                   unsigned long long b,
                                                   unsigned long long c) {
    unsigned long long d;
    asm("fma.rn.f32x2 %0, %1, %2, %3;" : "=l"(d) : "l"(a), "l"(b), "l"(c));
    return d;
}
__device__ __forceinline__ unsigned long long add2(unsigned long long a,
                                                   unsigned long long b) {
    unsigned long long d;
    asm("add.rn.f32x2 %0, %1, %2;" : "=l"(d) : "l"(a), "l"(b));
    return d;
}
__device__ __forceinline__ float sigmoidf_(float z) { return 1.0f / (1.0f + expf(-z)); }
__device__ __forceinline__ float cfc_mix(float a1, float a2, float ac,
                                         float b1, float b2, float bc) {
    float ff1 = tanhf(a1 + b1);
    float ff2 = tanhf(a2 + b2);
    float ti  = sigmoidf_(ac + bc);
    return ff1 + ti * (ff2 - ff1);
}

// ---------------------------------------------------------------------------
// Main persistent kernel: 64 CTAs x 480 threads, 4 batch rows each.
// Matmul thread = (mat, j-group-of-4, k-chunk); LDG.128 weights; 8 FFMA2/k.
// ---------------------------------------------------------------------------
__global__ __launch_bounds__(NTH, 1) void cfc_main_kernel(
    const float* __restrict__ x,
    const float* __restrict__ b1_0, const float* __restrict__ b2_0,
    const float* __restrict__ b1_1, const float* __restrict__ b2_1,
    const float* __restrict__ b1_2, const float* __restrict__ b2_2,
    float* __restrict__ out, int write_h)
{
    extern __shared__ float sm[];
    float* xh0d  = sm + OFF_XH0;
    float* xh1d  = sm + OFF_XH1;
    float* xh2   = sm + OFF_XH2;
    float* part  = sm + OFF_PART;
    float* part2 = sm + OFF_PART2;
    float* sw2   = sm + OFF_SW2;

    const int tid = threadIdx.x;
    const int b0  = blockIdx.x * ROWS;
    const int mat = tid / 160;
    const int rem = tid - mat * 160;
    const int jj  = rem;
    const int rsel = (mat == 0) ? 0 : mat;

    // matmul decomposition
    const int jg0 = rem % 40, kc0 = rem / 40;
    const int kb0 = kc0 * 70;
    int ke0 = kb0 + 70; if (ke0 > CAT0) ke0 = CAT0;
    const int jg1 = rem % 25, kc1 = rem / 25;
    const int kb1 = kc1 * 42;
    int ke1 = kb1 + 42; if (ke1 > CAT1) ke1 = CAT1;
    const bool act1 = (kc1 < 6);

    // ---- prologue ----
    for (int i = tid; i < 2216; i += NTH) xh0d[i] = 0.f;
    for (int i = tid; i < 1984; i += NTH) xh1d[i] = 0.f;
    for (int i = tid; i < 440;  i += NTH) xh2[i]  = 0.f;
    for (int i = tid; i < 3 * CAT2 * S2; i += NTH) sw2[i] = ((const float*)g_W2)[i];

    float rb1_0 = 0.f, rb2_0 = 0.f, rbc_0 = 0.f;
    float rb1_1 = 0.f, rb2_1 = 0.f, rbc_1 = 0.f;
    float rb1_2 = 0.f, rb2_2 = 0.f, rbc_2 = 0.f;
    if (jj < NI) { rb1_0 = b1_0[jj]; rb2_0 = b2_0[jj]; rbc_0 = g_bc[jj]; }
    if (jj < NC) { rb1_1 = b1_1[jj]; rb2_1 = b2_1[jj]; rbc_1 = g_bc[NI + jj]; }
    if (jj < NM) { rb1_2 = b1_2[jj]; rb2_2 = b2_2[jj]; rbc_2 = g_bc[NI + NC + jj]; }

    // stage x_0 (duplicated), prefetch x_1
    const int i0 = tid, i1 = tid + NTH;
    for (int i = tid; i < ROWS * IND; i += NTH) {
        int r = i >> 7, k = i & 127;
        float v = x[((size_t)(b0 + r) * TT + 0) * IND + k];
        *(unsigned long long*)&xh0d[k * 8 + r * 2] = pack2(v, v);
    }
    float xr0 = x[((size_t)(b0 + (i0 >> 7)) * TT + 1) * IND + (i0 & 127)];
    float xr1 = 0.f;
    if (i1 < ROWS * IND)
        xr1 = x[((size_t)(b0 + (i1 >> 7)) * TT + 1) * IND + (i1 & 127)];
    __syncthreads();

    for (int t = 0; t < TT; ++t) {
        // ============ (a) layer-0 partials ============
        {
            const ulonglong2* Wp =
                (const ulonglong2*)(g_W0[mat] + (size_t)kb0 * S0 + jg0 * 4);
            unsigned long long aA0 = 0, aB0 = 0, aA1 = 0, aB1 = 0;
            unsigned long long aA2 = 0, aB2 = 0, aA3 = 0, aB3 = 0;
            const float* ab = xh0d + kb0 * 8;
            #pragma unroll 5
            for (int k = kb0; k < ke0; ++k) {
                ulonglong2 w = *Wp; Wp += (S0 / 4);
                ulonglong2 d01 = *(const ulonglong2*)(ab);
                ulonglong2 d23 = *(const ulonglong2*)(ab + 4);
                ab += 8;
                aA0 = fma2(w.x, d01.x, aA0); aB0 = fma2(w.y, d01.x, aB0);
                aA1 = fma2(w.x, d01.y, aA1); aB1 = fma2(w.y, d01.y, aB1);
                aA2 = fma2(w.x, d23.x, aA2); aB2 = fma2(w.y, d23.x, aB2);
                aA3 = fma2(w.x, d23.y, aA3); aB3 = fma2(w.y, d23.y, aB3);
            }
            float* P = part + (size_t)((kc0 * 3 + mat) * 4) * 160 + jg0 * 4;
            *(ulonglong2*)(P)       = make_ulonglong2(aA0, aB0);
            *(ulonglong2*)(P + 160) = make_ulonglong2(aA1, aB1);
            *(ulonglong2*)(P + 320) = make_ulonglong2(aA2, aB2);
            *(ulonglong2*)(P + 480) = make_ulonglong2(aA3, aB3);
        }
        __syncthreads();

        // ============ (c) combine layer-0 + x restage ============
        if (jj < NI) {
            float a1 = 0.f, a2 = 0.f, ac = 0.f;
            #pragma unroll
            for (int c = 0; c < 4; ++c) {
                a1 += part[((c * 3 + 0) * 4 + rsel) * 160 + jj];
                a2 += part[((c * 3 + 1) * 4 + rsel) * 160 + jj];
                ac += part[((c * 3 + 2) * 4 + rsel) * 160 + jj];
            }
            float h = cfc_mix(a1, a2, ac, rb1_0, rb2_0, rbc_0);
            unsigned long long hh = pack2(h, h);
            *(unsigned long long*)&xh0d[(IND + jj) * 8 + rsel * 2] = hh;
            *(unsigned long long*)&xh1d[jj * 8 + rsel * 2]         = hh;
            if (mat == 0) {
                float c1 = 0.f, c2 = 0.f, cc = 0.f;
                #pragma unroll
                for (int c = 0; c < 4; ++c) {
                    c1 += part[((c * 3 + 0) * 4 + 3) * 160 + jj];
                    c2 += part[((c * 3 + 1) * 4 + 3) * 160 + jj];
                    cc += part[((c * 3 + 2) * 4 + 3) * 160 + jj];
                }
                float h3 = cfc_mix(c1, c2, cc, rb1_0, rb2_0, rbc_0);
                unsigned long long hh3 = pack2(h3, h3);
                *(unsigned long long*)&xh0d[(IND + jj) * 8 + 6] = hh3;
                *(unsigned long long*)&xh1d[jj * 8 + 6]         = hh3;
            }
        }
        {
            *(unsigned long long*)&xh0d[(i0 & 127) * 8 + (i0 >> 7) * 2] = pack2(xr0, xr0);
            if (i1 < ROWS * IND)
                *(unsigned long long*)&xh0d[(i1 & 127) * 8 + (i1 >> 7) * 2] = pack2(xr1, xr1);
            int tn = t + 2; if (tn > TT - 1) tn = TT - 1;
            xr0 = x[((size_t)(b0 + (i0 >> 7)) * TT + tn) * IND + (i0 & 127)];
            if (i1 < ROWS * IND)
                xr1 = x[((size_t)(b0 + (i1 >> 7)) * TT + tn) * IND + (i1 & 127)];
        }
        __syncthreads();

        // ============ (e) layer-1 partials ============
        if (act1) {
            const ulonglong2* Wp =
                (const ulonglong2*)(g_W1[mat] + (size_t)kb1 * S1 + jg1 * 4);
            unsigned long long aA0 = 0, aB0 = 0, aA1 = 0, aB1 = 0;
            unsigned long long aA2 = 0, aB2 = 0, aA3 = 0, aB3 = 0;
            const float* ab = xh1d + kb1 * 8;
            #pragma unroll 6
            for (int k = kb1; k < ke1; ++k) {
                ulonglong2 w = *Wp; Wp += (S1 / 4);
                ulonglong2 d01 = *(const ulonglong2*)(ab);
                ulonglong2 d23 = *(const ulonglong2*)(ab + 4);
                ab += 8;
                aA0 = fma2(w.x, d01.x, aA0); aB0 = fma2(w.y, d01.x, aB0);
                aA1 = fma2(w.x, d01.y, aA1); aB1 = fma2(w.y, d01.y, aB1);
                aA2 = fma2(w.x, d23.x, aA2); aB2 = fma2(w.y, d23.x, aB2);
                aA3 = fma2(w.x, d23.y, aA3); aB3 = fma2(w.y, d23.y, aB3);
            }
            float* P = part + (size_t)((kc1 * 3 + mat) * 4) * 128 + jg1 * 4;
            *(ulonglong2*)(P)       = make_ulonglong2(aA0, aB0);
            *(ulonglong2*)(P + 128) = make_ulonglong2(aA1, aB1);
            *(ulonglong2*)(P + 256) = make_ulonglong2(aA2, aB2);
            *(ulonglong2*)(P + 384) = make_ulonglong2(aA3, aB3);
        }
        __syncthreads();

        // ============ (g) combine layer-1 ============
        if (jj < NC) {
            float a1 = 0.f, a2 = 0.f, ac = 0.f;
            #pragma unroll
            for (int c = 0; c < 6; ++c) {
                a1 += part[((c * 3 + 0) * 4 + rsel) * 128 + jj];
                a2 += part[((c * 3 + 1) * 4 + rsel) * 128 + jj];
                ac += part[((c * 3 + 2) * 4 + rsel) * 128 + jj];
            }
            float h = cfc_mix(a1, a2, ac, rb1_1, rb2_1, rbc_1);
            *(unsigned long long*)&xh1d[(NI + jj) * 8 + rsel * 2] = pack2(h, h);
            xh2[jj * 4 + rsel] = h;
            if (mat == 0) {
                float c1 = 0.f, c2 = 0.f, cc = 0.f;
                #pragma unroll
                for (int c = 0; c < 6; ++c) {
                    c1 += part[((c * 3 + 0) * 4 + 3) * 128 + jj];
                    c2 += part[((c * 3 + 1) * 4 + 3) * 128 + jj];
                    cc += part[((c * 3 + 2) * 4 + 3) * 128 + jj];
                }
                float h3 = cfc_mix(c1, c2, cc, rb1_1, rb2_1, rbc_1);
                *(unsigned long long*)&xh1d[(NI + jj) * 8 + 6] = pack2(h3, h3);
                xh2[jj * 4 + 3] = h3;
            }
        }
        __syncthreads();

        // ============ (i) layer-2 partials ============
        {
            int j2 = jj & 7, kc2 = jj >> 3;
            int kb = kc2 * 6;
            int ke = kb + 6; if (ke > CAT2) ke = CAT2; if (kb > CAT2) kb = CAT2;
            unsigned long long p01 = 0, p23 = 0;
            const float* W = sw2 + mat * (CAT2 * S2) + j2;
            for (int k = kb; k < ke; ++k) {
                float w = W[k * 8];
                unsigned long long ww = pack2(w, w);
                ulonglong2 u = *(const ulonglong2*)&xh2[k * 4];
                p01 = fma2(ww, u.x, p01);
                p23 = fma2(ww, u.y, p23);
            }
            *(ulonglong2*)&part2[(mat * 160 + jj) * 4] = make_ulonglong2(p01, p23);
        }
        __syncthreads();

        // ============ (k) combine layer-2 (8 threads) ============
        if (mat == 0 && jj < NM) {
            unsigned long long s0a = 0, s0b = 0, s1a = 0, s1b = 0, s2a = 0, s2b = 0;
            #pragma unroll 4
            for (int kc = 0; kc < 20; ++kc) {
                int p = (kc * 8 + jj) * 4;
                ulonglong2 u0 = *(const ulonglong2*)&part2[p];
                ulonglong2 u1 = *(const ulonglong2*)&part2[640 + p];
                ulonglong2 u2 = *(const ulonglong2*)&part2[1280 + p];
                s0a = add2(s0a, u0.x); s0b = add2(s0b, u0.y);
                s1a = add2(s1a, u1.x); s1b = add2(s1b, u1.y);
                s2a = add2(s2a, u2.x); s2b = add2(s2b, u2.y);
            }
            float a1[4], a2[4], ac[4];
            unpack2(s0a, a1[0], a1[1]); unpack2(s0b, a1[2], a1[3]);
            unpack2(s1a, a2[0], a2[1]); unpack2(s1b, a2[2], a2[3]);
            unpack2(s2a, ac[0], ac[1]); unpack2(s2b, ac[2], ac[3]);
            #pragma unroll
            for (int r = 0; r < 4; ++r) {
                float h = cfc_mix(a1[r], a2[r], ac[r], rb1_2, rb2_2, rbc_2);
                xh2[(NC + jj) * 4 + r] = h;
                out[((size_t)(b0 + r) * TT + t) * NM + jj] = tanhf(h);
            }
        }
        // no barrier: next write to part2/xh2[NC+..] is ≥4 barriers away
    }

    __syncthreads();
    if (write_h) {
        size_t base = (size_t)BB * TT * NM;
        for (int pass = 0; pass < 2; ++pass) {
            int rr = (pass == 0) ? rsel : 3;
            if (pass == 1 && mat != 0) break;
            size_t ro = base + (size_t)(b0 + rr) * 256;
            if (jj < NI) out[ro + jj]           = xh0d[(IND + jj) * 8 + rr * 2];
            if (jj < NC) out[ro + NI + jj]      = xh1d[(NI + jj) * 8 + rr * 2];
            if (jj < NM) out[ro + NI + NC + jj] = xh2[(NC + jj) * 4 + rr];
        }
    }
}

// ---------------------------------------------------------------------------
extern "C" void kernel_launch(void* const* d_in, const int* in_sizes, int n_in,
                              void* d_out, int out_size)
{
    const float *x, *dt;
    const float *w1[3], *b1[3], *w2[3], *b2[3], *wa[3], *ba[3], *wb[3], *bb[3];
    const int   *m[3];

    if (in_sizes[0] == BB * TT * IND) {
        x  = (const float*)d_in[0];
        dt = (const float*)d_in[1];
        for (int l = 0; l < 3; l++) {
            int base = 2 + 9 * l;
            w1[l] = (const float*)d_in[base + 0];
            b1[l] = (const float*)d_in[base + 1];
            w2[l] = (const float*)d_in[base + 2];
            b2[l] = (const float*)d_in[base + 3];
            wa[l] = (const float*)d_in[base + 4];
            ba[l] = (const float*)d_in[base + 5];
            wb[l] = (const float*)d_in[base + 6];
            bb[l] = (const float*)d_in[base + 7];
            m[l]  = (const int*)  d_in[base + 8];
        }
    } else {
        for (int l = 0; l < 3; l++) {
            int base = 9 * l;
            w1[l] = (const float*)d_in[base + 0];
            w2[l] = (const float*)d_in[base + 1];
            wa[l] = (const float*)d_in[base + 2];
            wb[l] = (const float*)d_in[base + 3];
            b1[l] = (const float*)d_in[base + 4];
            b2[l] = (const float*)d_in[base + 5];
            ba[l] = (const float*)d_in[base + 6];
            bb[l] = (const float*)d_in[base + 7];
            m[l]  = (const int*)  d_in[base + 8];
        }
        x  = (const float*)d_in[27];
        dt = (const float*)d_in[28];
    }

    cfc_precompute_kernel<<<148, 256>>>(
        w1[0], w2[0], wa[0], wb[0], ba[0], bb[0], m[0],
        w1[1], w2[1], wa[1], wb[1], ba[1], bb[1], m[1],
        w1[2], w2[2], wa[2], wb[2], ba[2], bb[2], m[2],
        dt);

    cudaFuncSetAttribute(cfc_main_kernel,
                         cudaFuncAttributeMaxDynamicSharedMemorySize, SMEM_BYTES);

    int write_h = (out_size >= BB * TT * NM + BB * 256) ? 1 : 0;
    cfc_main_kernel<<<BB / ROWS, NTH, SMEM_BYTES>>>(
        x, b1[0], b2[0], b1[1], b2[1], b1[2], b2[2],
        (float*)d_out, write_h);
}